// round 8
// baseline (speedup 1.0000x reference)
#include <cuda_runtime.h>

// Problem constants (shapes fixed by the dataset)
#define SRC_SIZE 2000000
#define TABLE_SIZE (2 * SRC_SIZE)

// 16 MB scratch: concatenated gathered layer inputs (stage 1 output).
__device__ float g_layer[TABLE_SIZE];

// Stage 1: g_layer = concat(values_a[idx_a], values_b[idx_b]).
// 4 a-gathers + 4 b-gathers per thread (measured-best ILP). 128-thread
// blocks for finer wave granularity + early PDL trigger so stage2's
// launch flow overlaps stage1 execution.
__global__ void __launch_bounds__(128)
stage1_gather(const float* __restrict__ va,
              const float* __restrict__ vb,
              const int4*  __restrict__ ia4,
              const int4*  __restrict__ ib4,
              int quarter)                    // = src_size / 4
{
    int i = blockIdx.x * blockDim.x + threadIdx.x;

    int4 ja, jb;
    if (i < quarter) {
        ja = __ldcs(&ia4[i]);
        jb = __ldcs(&ib4[i]);
    }

    // Signal the dependent launch as early as possible (gates only the
    // LAUNCH of stage2; memory visibility is still enforced by
    // cudaGridDependencySynchronize in stage2).
    cudaTriggerProgrammaticLaunchCompletion();

    if (i >= quarter) return;

    float a0 = __ldcg(&va[ja.x]);
    float a1 = __ldcg(&va[ja.y]);
    float a2 = __ldcg(&va[ja.z]);
    float a3 = __ldcg(&va[ja.w]);
    float b0 = __ldcg(&vb[jb.x]);
    float b1 = __ldcg(&vb[jb.y]);
    float b2 = __ldcg(&vb[jb.z]);
    float b3 = __ldcg(&vb[jb.w]);

    float4* outa = (float4*)g_layer;
    float4* outb = (float4*)(g_layer + 4 * quarter);
    outa[i] = make_float4(a0, a1, a2, a3);
    outb[i] = make_float4(b0, b1, b2, b3);
}

// Stage 2 with PDL: prefetch indices + weights (independent of stage 1),
// then wait for stage 1's memory, then gather. Pinned at the L1tex
// wavefront floor (~116 us).
__global__ void __launch_bounds__(256)
stage2_rule(const int4* __restrict__ cidx4,   // 2 int4s per neuron
            const float* __restrict__ w,      // 8 weights
            float* __restrict__ out,
            int num_neurons)
{
    int t = blockIdx.x * blockDim.x + threadIdx.x;

    int4 c0, c1;
    float w0, w1, w2, w3, w4, w5, w6, w7;
    if (t < num_neurons) {
        // Prefetch: none of this depends on g_layer — overlaps stage 1's tail.
        c0 = __ldcs(&cidx4[2 * t]);
        c1 = __ldcs(&cidx4[2 * t + 1]);
        w0 = __ldg(&w[0]); w1 = __ldg(&w[1]); w2 = __ldg(&w[2]); w3 = __ldg(&w[3]);
        w4 = __ldg(&w[4]); w5 = __ldg(&w[5]); w6 = __ldg(&w[6]); w7 = __ldg(&w[7]);
    }

    // Wait for stage 1 (prior grid) to complete and flush.
    cudaGridDependencySynchronize();

    if (t >= num_neurons) return;

    // 8 independent random gathers (MLP = 8), L2-only
    float v0 = __ldcg(&g_layer[c0.x]);
    float v1 = __ldcg(&g_layer[c0.y]);
    float v2 = __ldcg(&g_layer[c0.z]);
    float v3 = __ldcg(&g_layer[c0.w]);
    float v4 = __ldcg(&g_layer[c1.x]);
    float v5 = __ldcg(&g_layer[c1.y]);
    float v6 = __ldcg(&g_layer[c1.z]);
    float v7 = __ldcg(&g_layer[c1.w]);

    float s = v0 * w0;
    s = fmaf(v1, w1, s);
    s = fmaf(v2, w2, s);
    s = fmaf(v3, w3, s);
    s = fmaf(v4, w4, s);
    s = fmaf(v5, w5, s);
    s = fmaf(v6, w6, s);
    s = fmaf(v7, w7, s);

    __stcs(&out[t], tanhf(s));
}

extern "C" void kernel_launch(void* const* d_in, const int* in_sizes, int n_in,
                              void* d_out, int out_size)
{
    // metadata order: values_a, values_b, weights, idx_a, idx_b, concat_idx
    const float* va   = (const float*)d_in[0];
    const float* vb   = (const float*)d_in[1];
    const float* w    = (const float*)d_in[2];
    const int*   ia   = (const int*)d_in[3];
    const int*   ib   = (const int*)d_in[4];
    const int*   cidx = (const int*)d_in[5];
    float* out = (float*)d_out;

    int src_size    = in_sizes[0];      // 2,000,000 (divisible by 4)
    int num_neurons = out_size;         // 4,000,000

    {
        int quarter = src_size / 4;
        int threads = 128;
        int blocks = (quarter + threads - 1) / threads;
        stage1_gather<<<blocks, threads>>>(va, vb,
                                           (const int4*)ia, (const int4*)ib,
                                           quarter);
    }
    {
        int threads = 256;
        int blocks = (num_neurons + threads - 1) / threads;

        // PDL launch: stage2 blocks may start while stage1 drains;
        // cudaGridDependencySynchronize() inside guards the g_layer reads.
        cudaLaunchConfig_t cfg = {};
        cfg.gridDim  = dim3((unsigned)blocks, 1, 1);
        cfg.blockDim = dim3((unsigned)threads, 1, 1);
        cfg.dynamicSmemBytes = 0;
        cfg.stream = 0;
        cudaLaunchAttribute attr[1];
        attr[0].id = cudaLaunchAttributeProgrammaticStreamSerialization;
        attr[0].val.programmaticStreamSerializationAllowed = 1;
        cfg.attrs = attr;
        cfg.numAttrs = 1;

        cudaLaunchKernelEx(&cfg, stage2_rule,
                           (const int4*)cidx, w, out, num_neurons);
    }
}

// round 9
// speedup vs baseline: 1.0146x; 1.0146x over previous
#include <cuda_runtime.h>

// Problem constants (shapes fixed by the dataset)
#define SRC_SIZE 2000000
#define TABLE_SIZE (2 * SRC_SIZE)

// 16 MB scratch: concatenated gathered layer inputs (stage 1 output).
__device__ float g_layer[TABLE_SIZE];

// Hardware tanh approximation (sm_75+): |err| ~ 2^-11, far inside the 1e-3
// budget; replaces the ~20-instruction tanhf polynomial with one MUFU op.
__device__ __forceinline__ float tanh_approx(float x) {
    float y;
    asm("tanh.approx.f32 %0, %1;" : "=f"(y) : "f"(x));
    return y;
}

// Stage 1: g_layer = concat(values_a[idx_a], values_b[idx_b]).
// 4 a-gathers + 4 b-gathers per thread (measured-best ILP), 256-thr blocks.
__global__ void __launch_bounds__(256)
stage1_gather(const float* __restrict__ va,
              const float* __restrict__ vb,
              const int4*  __restrict__ ia4,
              const int4*  __restrict__ ib4,
              int quarter)                    // = src_size / 4
{
    int i = blockIdx.x * blockDim.x + threadIdx.x;

    int4 ja, jb;
    if (i < quarter) {
        ja = __ldcs(&ia4[i]);
        jb = __ldcs(&ib4[i]);
    }

    // Release the dependent launch early (gates only stage2's LAUNCH;
    // memory visibility is enforced by cudaGridDependencySynchronize).
    cudaTriggerProgrammaticLaunchCompletion();

    if (i >= quarter) return;

    float a0 = __ldcg(&va[ja.x]);
    float a1 = __ldcg(&va[ja.y]);
    float a2 = __ldcg(&va[ja.z]);
    float a3 = __ldcg(&va[ja.w]);
    float b0 = __ldcg(&vb[jb.x]);
    float b1 = __ldcg(&vb[jb.y]);
    float b2 = __ldcg(&vb[jb.z]);
    float b3 = __ldcg(&vb[jb.w]);

    float4* outa = (float4*)g_layer;
    float4* outb = (float4*)(g_layer + 4 * quarter);
    outa[i] = make_float4(a0, a1, a2, a3);
    outb[i] = make_float4(b0, b1, b2, b3);
}

// Stage 2 with PDL: prefetch indices + weights (independent of stage 1),
// wait for stage 1's memory, gather, weighted sum, hw-tanh, store.
// Pinned at the L1tex wavefront floor (~116 us for 32M gather wavefronts).
__global__ void __launch_bounds__(256)
stage2_rule(const int4* __restrict__ cidx4,   // 2 int4s per neuron
            const float* __restrict__ w,      // 8 weights
            float* __restrict__ out,
            int num_neurons)
{
    int t = blockIdx.x * blockDim.x + threadIdx.x;

    int4 c0, c1;
    float w0, w1, w2, w3, w4, w5, w6, w7;
    if (t < num_neurons) {
        // Prefetch: none of this depends on g_layer — overlaps stage 1's tail.
        c0 = __ldcs(&cidx4[2 * t]);
        c1 = __ldcs(&cidx4[2 * t + 1]);
        w0 = __ldg(&w[0]); w1 = __ldg(&w[1]); w2 = __ldg(&w[2]); w3 = __ldg(&w[3]);
        w4 = __ldg(&w[4]); w5 = __ldg(&w[5]); w6 = __ldg(&w[6]); w7 = __ldg(&w[7]);
    }

    // Wait for stage 1 (prior grid) to complete and flush.
    cudaGridDependencySynchronize();

    if (t >= num_neurons) return;

    // 8 independent random gathers (MLP = 8), L2-only
    float v0 = __ldcg(&g_layer[c0.x]);
    float v1 = __ldcg(&g_layer[c0.y]);
    float v2 = __ldcg(&g_layer[c0.z]);
    float v3 = __ldcg(&g_layer[c0.w]);
    float v4 = __ldcg(&g_layer[c1.x]);
    float v5 = __ldcg(&g_layer[c1.y]);
    float v6 = __ldcg(&g_layer[c1.z]);
    float v7 = __ldcg(&g_layer[c1.w]);

    float s = v0 * w0;
    s = fmaf(v1, w1, s);
    s = fmaf(v2, w2, s);
    s = fmaf(v3, w3, s);
    s = fmaf(v4, w4, s);
    s = fmaf(v5, w5, s);
    s = fmaf(v6, w6, s);
    s = fmaf(v7, w7, s);

    __stcs(&out[t], tanh_approx(s));
}

extern "C" void kernel_launch(void* const* d_in, const int* in_sizes, int n_in,
                              void* d_out, int out_size)
{
    // metadata order: values_a, values_b, weights, idx_a, idx_b, concat_idx
    const float* va   = (const float*)d_in[0];
    const float* vb   = (const float*)d_in[1];
    const float* w    = (const float*)d_in[2];
    const int*   ia   = (const int*)d_in[3];
    const int*   ib   = (const int*)d_in[4];
    const int*   cidx = (const int*)d_in[5];
    float* out = (float*)d_out;

    int src_size    = in_sizes[0];      // 2,000,000 (divisible by 4)
    int num_neurons = out_size;         // 4,000,000

    {
        int quarter = src_size / 4;
        int threads = 256;
        int blocks = (quarter + threads - 1) / threads;
        stage1_gather<<<blocks, threads>>>(va, vb,
                                           (const int4*)ia, (const int4*)ib,
                                           quarter);
    }
    {
        int threads = 256;
        int blocks = (num_neurons + threads - 1) / threads;   // 15625 exact

        // PDL launch: stage2 blocks may start while stage1 drains;
        // cudaGridDependencySynchronize() inside guards the g_layer reads.
        cudaLaunchConfig_t cfg = {};
        cfg.gridDim  = dim3((unsigned)blocks, 1, 1);
        cfg.blockDim = dim3((unsigned)threads, 1, 1);
        cfg.dynamicSmemBytes = 0;
        cfg.stream = 0;
        cudaLaunchAttribute attr[1];
        attr[0].id = cudaLaunchAttributeProgrammaticStreamSerialization;
        attr[0].val.programmaticStreamSerializationAllowed = 1;
        cfg.attrs = attr;
        cfg.numAttrs = 1;

        cudaLaunchKernelEx(&cfg, stage2_rule,
                           (const int4*)cidx, w, out, num_neurons);
    }
}